// round 7
// baseline (speedup 1.0000x reference)
#include <cuda_runtime.h>
#include <math_constants.h>

static constexpr int   N_ATOMS = 256;
static constexpr float RCUT    = 6.0f;
static constexpr float RCUT2   = 36.0f;
static constexpr int   NFEAT   = 24;
static constexpr int   MAXA    = 512;       // max total atoms (B<=2)
static constexpr int   CCHUNK  = 592;       // 148 SMs * 4 CTAs, one wave
static constexpr int   MAXSLOT = 24;

// persistent scratch (device globals; no allocation)
__device__ float4       g_dA[MAXA][N_ATOMS];   // dx, dy, dz, sq
__device__ float4       g_dB[MAXA][N_ATOMS];   // fc*e^{-.01sq}, fc*e^{-.1sq}, 1/r, fc
__device__ int          g_M[MAXA];
__device__ unsigned int g_P[MAXA + 1];         // pair-count prefix sums
__device__ float        g_slot[MAXA][MAXSLOT][16];

// packed f32x2 helpers (Blackwell fma.rn.f32x2)
__device__ __forceinline__ unsigned long long pk2(float lo, float hi) {
    unsigned long long d;
    asm("mov.b64 %0, {%1, %2};" : "=l"(d)
        : "r"(__float_as_uint(lo)), "r"(__float_as_uint(hi)));
    return d;
}
__device__ __forceinline__ void upk2(unsigned long long v, float& lo, float& hi) {
    unsigned int a, b;
    asm("mov.b64 {%0, %1}, %2;" : "=r"(a), "=r"(b) : "l"(v));
    lo = __uint_as_float(a); hi = __uint_as_float(b);
}
__device__ __forceinline__ unsigned long long ffma2(unsigned long long a,
                                                    unsigned long long b,
                                                    unsigned long long c) {
    unsigned long long d;
    asm("fma.rn.f32x2 %0, %1, %2, %3;" : "=l"(d) : "l"(a), "l"(b), "l"(c));
    return d;
}

// ---------------- K1: neighbor tables + radial features ----------------
__global__ __launch_bounds__(256)
void k1_build(const float* __restrict__ zn,
              const float* __restrict__ coords,
              float* __restrict__ out)
{
    const int i    = blockIdx.x;
    const int b    = blockIdx.y;
    const int q    = b * N_ATOMS + i;
    const int tid  = threadIdx.x;
    const int lane = tid & 31;
    const int wid  = tid >> 5;

    __shared__ float radw[7][8];
    __shared__ int   wcnt[8], woff[8], sM;

    const float* cb = coords + (size_t)b * N_ATOMS * 3;
    const float xi = cb[3*i+0], yi = cb[3*i+1], zi = cb[3*i+2];

    const int   j  = tid;
    const float dx = xi - cb[3*j+0];
    const float dy = yi - cb[3*j+1];
    const float dz = zi - cb[3*j+2];
    const float sq = dx*dx + dy*dy + dz*dz;
    const bool  valid = (j != i) && (sq < RCUT2);
    const float r  = sqrtf(sq);
    const float fc = valid ? 0.5f * (__cosf(CUDART_PI_F * r * (1.0f/RCUT)) + 1.0f)
                           : 0.0f;

    float g[7];
    {
        const float rm2 = r - 2.0f;
        g[0] = fc;
        g[1] = __expf(-0.1f * sq        ) * fc;
        g[2] = __expf(-1.0f * sq        ) * fc;
        g[3] = __expf(-0.1f * rm2 * rm2 ) * fc;
        g[4] = __expf(-1.0f * rm2 * rm2 ) * fc;
        g[5] = __cosf(1.0f * r) * fc;
        g[6] = __cosf(2.0f * r) * fc;
    }
#pragma unroll
    for (int f = 0; f < 7; f++) {
        float v = g[f];
#pragma unroll
        for (int s = 16; s > 0; s >>= 1) v += __shfl_down_sync(0xffffffffu, v, s);
        if (lane == 0) radw[f][wid] = v;
    }

    const unsigned bm = __ballot_sync(0xffffffffu, valid);
    const int before = __popc(bm & ((1u << lane) - 1u));
    if (lane == 0) wcnt[wid] = __popc(bm);
    __syncthreads();
    if (tid == 0) {
        int o = 0;
#pragma unroll
        for (int w = 0; w < 8; w++) { woff[w] = o; o += wcnt[w]; }
        sM = o;
    }
    __syncthreads();
    if (valid) {
        const int p = woff[wid] + before;
        g_dA[q][p] = make_float4(dx, dy, dz, sq);
        const float e01 = __expf(-0.01f * sq);
        const float e10 = __expf(-0.1f  * sq);
        g_dB[q][p] = make_float4(fc * e01, fc * e10, rsqrtf(sq), fc);
    }
    if (tid == 0) {
        g_M[q] = sM;
        float* o = out + (size_t)q * NFEAT;
        o[0] = zn[i];
#pragma unroll
        for (int f = 0; f < 7; f++) {
            float s = 0.0f;
#pragma unroll
            for (int w = 0; w < 8; w++) s += radw[f][w];
            o[1 + f] = s;
        }
    }
}

// ---------------- K2: prefix scan of pair counts ----------------
__global__ __launch_bounds__(MAXA)
void k2_scan(int A)
{
    __shared__ unsigned int sv[MAXA];
    const int t = threadIdx.x;
    unsigned int n = 0;
    if (t < A) {
        const int M = g_M[t];
        n = (unsigned int)(M * (M - 1) / 2);
    }
    sv[t] = n;
    __syncthreads();
    for (int off = 1; off < MAXA; off <<= 1) {
        unsigned int v = (t >= off) ? sv[t - off] : 0u;
        __syncthreads();
        sv[t] += v;
        __syncthreads();
    }
    g_P[t + 1] = sv[t];
    if (t == 0) g_P[0] = 0u;
}

// ---------------- K3: equal-work angular chunks ----------------
__global__ __launch_bounds__(256, 4)
void k3_angular()
{
    const int c    = blockIdx.x;
    const int tid  = threadIdx.x;
    const int lane = tid & 31;
    const int wid  = tid >> 5;

    __shared__ float4       sA[N_ATOMS];
    __shared__ float4       sB[N_ATOMS];
    __shared__ unsigned int sP[MAXA + 1];
    __shared__ float        sRed[8][16];

    for (int t = tid; t < MAXA + 1; t += 256) sP[t] = g_P[t];
    __syncthreads();

    const unsigned long long T     = sP[MAXA];
    const unsigned long long start = ((unsigned long long)c       * T) / CCHUNK;
    const unsigned long long end   = ((unsigned long long)(c + 1) * T) / CCHUNK;
    if (start >= end) return;

    // largest a with sP[a] <= start
    int lo = 0, hi = MAXA;
    while (hi - lo > 1) {
        const int mid = (lo + hi) >> 1;
        if ((unsigned long long)sP[mid] <= start) lo = mid; else hi = mid;
    }
    int a = lo;
    unsigned long long pos = start;

    // fc(s) = fma(0.5*v, poly(v), 1), v = pi^2 s / 36  (deg-8 Taylor of cos)
    const float C1 = -0.5f;
    const float C2 =  1.0f / 24.0f;
    const float C3 = -1.0f / 720.0f;
    const float C4 =  1.0f / 40320.0f;
    const float C5 = -1.0f / 3628800.0f;
    const float C6 =  1.0f / 479001600.0f;
    const float C7 = -1.0f / 87178291200.0f;
    const float C8 =  1.0f / 20922789888000.0f;
    const float VSC = CUDART_PI_F * CUDART_PI_F / 36.0f;

    while (pos < end) {
        const unsigned int Pa  = sP[a];
        const unsigned int Pa1 = sP[a + 1];
        if ((unsigned long long)Pa1 <= pos) { a++; continue; }
        const unsigned long long seg_end =
            ((unsigned long long)Pa1 < end) ? (unsigned long long)Pa1 : end;

        const int M = g_M[a];
        for (int t = tid; t < M; t += 256) { sA[t] = g_dA[a][t]; sB[t] = g_dB[a][t]; }
        __syncthreads();

        unsigned long long acc[8];
#pragma unroll
        for (int f = 0; f < 8; f++) acc[f] = 0ull;

        const int l0 = (int)(pos - Pa);
        const int l1 = (int)(seg_end - Pa);
        for (int l = l0 + tid; l < l1; l += 256) {
            int k = (int)((sqrtf(8.0f * (float)l + 1.0f) + 1.0f) * 0.5f);
            while (k * (k - 1) / 2 > l)  k--;
            while ((k + 1) * k / 2 <= l) k++;
            const int jj = l - k * (k - 1) / 2;

            const float4 aj = sA[jj];
            const float4 ak = sA[k];
            const float4 bj = sB[jj];
            const float4 bk = sB[k];

            const float dot  = aj.x*ak.x + aj.y*ak.y + aj.z*ak.z;
            const float cth  = dot * bj.z * bk.z;
            const float sq2  = aj.w + ak.w;
            const float sqjk = fmaf(-2.0f, dot, sq2);

            const float v  = sqjk * VSC;
            float poly = fmaf(C8, v, C7);
            poly = fmaf(poly, v, C6);  poly = fmaf(poly, v, C5);
            poly = fmaf(poly, v, C4);  poly = fmaf(poly, v, C3);
            poly = fmaf(poly, v, C2);  poly = fmaf(poly, v, C1);
            float fcjk = fmaf(0.5f * v, poly, 1.0f);
            fcjk = (sqjk < RCUT2) ? fcjk : 0.0f;

            const float e2a = bj.x * bk.x;
            const float e2b = bj.y * bk.y;

            const float t   = __expf(-0.01f * sqjk);
            const float t2  = t * t, t4 = t2 * t2;
            const float t10 = t4 * t4 * t2;

            const float e3a = e2a * (t   * fcjk);
            const float e3b = e2b * (t10 * fcjk);

            const float p  = fmaxf(1.0f + cth, 0.0f);
            const float m  = fmaxf(1.0f - cth, 0.0f);
            const float p2 = p*p, p4 = p2*p2;
            const float m2 = m*m, m4 = m2*m2;

            const unsigned long long Ea = pk2(e3a, e2a);
            const unsigned long long Eb = pk2(e3b, e2b);
            const unsigned long long Mv = pk2(m,  m );
            const unsigned long long Pv = pk2(p,  p );
            const unsigned long long M4 = pk2(m4, m4);
            const unsigned long long P4 = pk2(p4, p4);

            acc[0] = ffma2(Mv, Ea, acc[0]);
            acc[1] = ffma2(Pv, Ea, acc[1]);
            acc[2] = ffma2(M4, Ea, acc[2]);
            acc[3] = ffma2(P4, Ea, acc[3]);
            acc[4] = ffma2(Mv, Eb, acc[4]);
            acc[5] = ffma2(Pv, Eb, acc[5]);
            acc[6] = ffma2(M4, Eb, acc[6]);
            acc[7] = ffma2(P4, Eb, acc[7]);
        }

        // reduce 16 features across the CTA (fixed order -> deterministic)
#pragma unroll
        for (int f = 0; f < 8; f++) {
            float v3, v2;
            upk2(acc[f], v3, v2);
#pragma unroll
            for (int s = 16; s > 0; s >>= 1) {
                v3 += __shfl_down_sync(0xffffffffu, v3, s);
                v2 += __shfl_down_sync(0xffffffffu, v2, s);
            }
            if (lane == 0) { sRed[wid][f] = v3; sRed[wid][8 + f] = v2; }
        }
        __syncthreads();

        if (tid < 16) {
            float s = 0.0f;
#pragma unroll
            for (int w = 0; w < 8; w++) s += sRed[w][tid];
            // slot = c - c_first(a);  c_first = ceil(C*(Pa+1)/T) - 1
            const unsigned long long cf =
                ((unsigned long long)CCHUNK * (Pa + 1) + T - 1) / T - 1;
            int slot = c - (int)cf;
            if (slot < 0) slot = 0;
            if (slot >= MAXSLOT) slot = MAXSLOT - 1;
            g_slot[a][slot][tid] = s;
        }
        __syncthreads();

        pos = seg_end;
        a++;
    }
}

// ---------------- K4: per-atom combine ----------------
__global__ __launch_bounds__(16)
void k4_combine(float* __restrict__ out)
{
    const int q = blockIdx.x;
    const int f = threadIdx.x;      // 0..15
    const unsigned int Pa  = g_P[q];
    const unsigned int Pa1 = g_P[q + 1];
    float s = 0.0f;
    if (Pa1 > Pa) {
        const unsigned long long T = g_P[MAXA];
        const unsigned long long cf =
            ((unsigned long long)CCHUNK * (Pa + 1) + T - 1) / T - 1;
        const unsigned long long cl =
            ((unsigned long long)CCHUNK * Pa1 - 1) / T;
        int ns = (int)(cl - cf) + 1;
        if (ns > MAXSLOT) ns = MAXSLOT;
        for (int sl = 0; sl < ns; sl++) s += g_slot[q][sl][f];
    }
    const float sc8[8] = {2.0f, 2.0f, 0.25f, 0.25f, 2.0f, 2.0f, 0.25f, 0.25f};
    float* o = out + (size_t)q * NFEAT;
    if (f < 8) o[8 + f]        = s * sc8[f];
    else       o[16 + (f - 8)] = s * sc8[f - 8];
}

extern "C" void kernel_launch(void* const* d_in, const int* in_sizes, int n_in,
                              void* d_out, int out_size)
{
    const float* zn     = (const float*)d_in[0];   // atomic_numbers [N]
    const float* coords = (const float*)d_in[1];   // coordinates   [B, N, 3]
    float*       out    = (float*)d_out;           // [B, N, 24]

    const int B = in_sizes[1] / (N_ATOMS * 3);
    const int A = B * N_ATOMS;

    k1_build  <<<dim3(N_ATOMS, B), 256>>>(zn, coords, out);
    k2_scan   <<<1, MAXA>>>(A);
    k3_angular<<<CCHUNK, 256>>>();
    k4_combine<<<A, 16>>>(out);
}